// round 11
// baseline (speedup 1.0000x reference)
#include <cuda_runtime.h>

// ConvCaps: votes = broadcast elementwise product, act_out = patch gather.
//
// votes[b,oh,ow,ky,kx,i,o,m,n] = poses[b,oh+ky,ow+kx,i,m,n] * K[ky,kx,i,o,m,n]
// act_out[b,oh,ow,ky,kx,i]     = activations[b,oh+ky,ow+kx,i]
//
// B=4 H=W=16 OH=OW=14 K=3 I=O=32 atoms 4x4. votes = 462 MB of stores ->
// DRAM-write-bound. 512-thread blocks cover 4 consecutive in-capsule slabs,
// so each spatial step emits one 8KB fully-contiguous write burst (vs 2KB
// before); weights still live entirely in registers (1 float4/thread).

constexpr int B = 4, H = 16, W = 16, OH = 14, OW = 14;
constexpr int IC = 32;
constexpr long VOTES_FLOATS = 115605504L;  // 4*14*14*9*32*32*16
constexpr int ACT_F4 = 56448;              // 225792 / 4
constexpr int ROWPAIRS = B * OH / 2;       // 28 (block = 2 output rows)
constexpr int IGROUPS = IC / 4;            // 8 groups of 4 in-capsules
constexpr int GROUPS = 9 * IGROUPS;        // 72 (kykx, igroup)
constexpr int VBLOCKS = ROWPAIRS * GROUPS; // 2016
constexpr int ABLOCKS = (ACT_F4 + 511) / 512;  // 111
constexpr int OUT_STRIDE_S = 9 * IC * 128; // float4 stride between spatial s

__global__ __launch_bounds__(512) void convcaps_fused(
    const float4* __restrict__ poses,   // [B,H,W,IC,4,4] as float4
    const float4* __restrict__ acts,    // [B,H,W,IC] as float4 (8 per pos)
    const float4* __restrict__ kern,    // [3,3,IC,OC,4,4] as float4
    float4* __restrict__ votes_out,
    float4* __restrict__ act_out)
{
    const int t = threadIdx.x;          // 0..511

    if (blockIdx.x < ABLOCKS) {
        // ---- activation patch gather (tiny; hides under wave-1 spin-up)
        int idx = blockIdx.x * 512 + t;
        if (idx < ACT_F4) {
            int i4 = idx & 7;
            int r  = idx >> 3;
            int kx = r % 3;  r /= 3;
            int ky = r % 3;  r /= 3;
            int ow = r % OW; r /= OW;
            int oh = r % OH;
            int b  = r / OH;
            act_out[idx] =
                __ldg(&acts[((b * H + oh + ky) * W + ow + kx) * 8 + i4]);
        }
        return;
    }

    // ---- votes: grid order (rowpair major, kykx, igroup fastest)
    int blk = blockIdx.x - ABLOCKS;
    const int g  = blk % GROUPS;        // kykx*IGROUPS + igroup
    const int rp = blk / GROUPS;
    const int ig   = g % IGROUPS;
    const int kykx = g / IGROUPS;       // 0..8
    const int ky = kykx / 3;
    const int kx = kykx - ky * 3;

    const int tt = t & 127;             // o*4 + m within slab
    const int i  = ig * 4 + (t >> 7);   // this thread's in-capsule
    const int m  = tt & 3;

    // Weight float4 pinned in registers for the whole block lifetime.
    const float4 kf = kern[(kykx * IC + i) * 128 + tt];

    // Block covers output rows row0, row0+1 (never straddles batch b).
    const int row0 = rp * 2;            // global output row (b*OH + oh)
    const int b   = row0 / OH;
    const int oh0 = row0 - b * OH;

    // Pose pointer at (b, oh0+ky, kx, i, m); +128 f4 per ow, +2048 f4 per row.
    const float4* pp =
        poses + ((((b * H + oh0 + ky) * W + kx) * IC + i) * 4 + m);
    // Output pointer at s = row0*OW; +OUT_STRIDE_S f4 per s.
    float4* op =
        votes_out + (((long)(row0 * OW) * 9 + kykx) * IC + i) * 128 + tt;

    #pragma unroll
    for (int r = 0; r < 2; ++r) {
        #pragma unroll
        for (int ow = 0; ow < OW; ++ow) {
            float4 p = __ldg(pp + ow * (IC * 4));
            float4 v;
            v.x = p.x * kf.x;
            v.y = p.y * kf.y;
            v.z = p.z * kf.z;
            v.w = p.w * kf.w;
            __stcs(op + ow * OUT_STRIDE_S, v);
        }
        pp += W * IC * 4;               // next input row
        op += (long)OW * OUT_STRIDE_S;  // next output row
    }
}

extern "C" void kernel_launch(void* const* d_in, const int* in_sizes, int n_in,
                              void* d_out, int out_size)
{
    const float4* poses = (const float4*)d_in[0];
    const float4* acts  = (const float4*)d_in[1];
    const float4* kern  = (const float4*)d_in[2];

    float* out_f = (float*)d_out;
    float4* votes_out = (float4*)out_f;
    float4* act_out   = (float4*)(out_f + VOTES_FLOATS);

    convcaps_fused<<<ABLOCKS + VBLOCKS, 512>>>(poses, acts, kern,
                                               votes_out, act_out);
}